// round 8
// baseline (speedup 1.0000x reference)
#include <cuda_runtime.h>
#include <cuda_bf16.h>
#include <cstdint>

#define NN 50000
#define EE 800000
#define CC 128
#define NEG 0.01f

// Scratch (no allocation allowed -> __device__ globals)
__device__ float g_y[NN * CC];
__device__ float g_aggr[NN * CC];
__device__ float g_delta[NN * 3];
__device__ int   g_is64;
// Fragment-major weights: per matrix 4096 x uint4 {bhi0,bhi1,blo0,blo1} = 64KB
// index (per matrix): ct*256 + kc*32 + g*4 + q
__device__ uint4 g_fragW[4 * 4096];
// Pre-split bf16 hi/lo A images, fragment-pair layout: [row][64] uint32 where
// s = kc*8 + 2q + j  maps to pair p = kc*8 + q + 4j  (cols 2p, 2p+1)
__device__ uint32_t g_xhi[NN * 64], g_xlo[NN * 64];
__device__ uint32_t g_ahi[NN * 64], g_alo[NN * 64];
__device__ uint32_t g_thi[NN * 64], g_tlo[NN * 64];

__device__ __forceinline__ float leaky(float v) {
    return v >= 0.0f ? v : NEG * v;
}

// ---------------------------------------------------------------------------
__global__ void detect_dtype_kernel(const int* __restrict__ ei32, int n_words)
{
    if (blockIdx.x == 0 && threadIdx.x == 0) {
        int all_hi_zero = 1;
        int pairs = n_words / 2;
        if (pairs > 1024) pairs = 1024;
        for (int p = 0; p < pairs; ++p) {
            if (ei32[2 * p + 1] != 0) { all_hi_zero = 0; break; }
        }
        g_is64 = all_hi_zero;
    }
}

// ---------------------------------------------------------------------------
__device__ __forceinline__ uint32_t pack_hi(float a, float b) {
    __nv_bfloat16 ha = __float2bfloat16(a), hb = __float2bfloat16(b);
    return (uint32_t)__bfloat16_as_ushort(ha) | ((uint32_t)__bfloat16_as_ushort(hb) << 16);
}
__device__ __forceinline__ uint32_t pack_lo(float a, float b) {
    __nv_bfloat16 ha = __float2bfloat16(a), hb = __float2bfloat16(b);
    __nv_bfloat16 la = __float2bfloat16(a - __bfloat162float(ha));
    __nv_bfloat16 lb = __float2bfloat16(b - __bfloat162float(hb));
    return (uint32_t)__bfloat16_as_ushort(la) | ((uint32_t)__bfloat16_as_ushort(lb) << 16);
}

__global__ void prep_weights_kernel(const float* __restrict__ w0,
                                    const float* __restrict__ w1,
                                    const float* __restrict__ w2,
                                    const float* __restrict__ w3)
{
    int idx = blockIdx.x * 256 + threadIdx.x;   // 4*4096 entries
    if (idx >= 4 * 4096) return;
    int m = idx >> 12;
    int rem = idx & 4095;
    int col = rem >> 5;        // 0..127
    int kc  = (rem >> 2) & 7;  // 0..7
    int q   = rem & 3;         // 0..3
    const float* w = (m == 0) ? w0 : (m == 1) ? w1 : (m == 2) ? w2 : w3;
    int k0 = kc * 16 + 2 * q;
    float a0 = w[(k0 + 0) * CC + col];
    float a1 = w[(k0 + 1) * CC + col];
    float a2 = w[(k0 + 8) * CC + col];
    float a3 = w[(k0 + 9) * CC + col];
    uint4 v;
    v.x = pack_hi(a0, a1);
    v.y = pack_hi(a2, a3);
    v.z = pack_lo(a0, a1);
    v.w = pack_lo(a2, a3);
    int ct = col >> 3, g = col & 7;
    g_fragW[m * 4096 + ct * 256 + kc * 32 + g * 4 + q] = v;
}

// ---------------------------------------------------------------------------
// Split fp32 [M,128] into bf16 hi/lo packed uint32 [M,64], fragment-pair layout.
// ---------------------------------------------------------------------------
__global__ void cvt_split_kernel(const float* __restrict__ src,
                                 uint32_t* __restrict__ hi,
                                 uint32_t* __restrict__ lo, int n)
{
    int idx = blockIdx.x * 256 + threadIdx.x;   // n = M*64
    if (idx >= n) return;
    int row = idx >> 6, s = idx & 63;
    int kc = s >> 3, r = s & 7, q = r >> 1, j = r & 1;
    int p = kc * 8 + q + 4 * j;
    float2 v = *(const float2*)(src + (size_t)row * CC + 2 * p);
    hi[idx] = pack_hi(v.x, v.y);
    lo[idx] = pack_lo(v.x, v.y);
}

// ---------------------------------------------------------------------------
__device__ __forceinline__ void mma_bf16(float* c, const uint32_t* a, const uint32_t* b)
{
    asm volatile(
        "mma.sync.aligned.m16n8k16.row.col.f32.bf16.bf16.f32 "
        "{%0,%1,%2,%3}, {%4,%5,%6,%7}, {%8,%9}, {%0,%1,%2,%3};"
        : "+f"(c[0]), "+f"(c[1]), "+f"(c[2]), "+f"(c[3])
        : "r"(a[0]), "r"(a[1]), "r"(a[2]), "r"(a[3]), "r"(b[0]), "r"(b[1]));
}

// ---------------------------------------------------------------------------
// Split-bf16 GEMM, pre-converted A (hi/lo uint32 [M,64]).
// smem: sAhi [128][40]u32 20480B; sAlo 20480B; W 65536B; bias 512; hw2 1536.
// 2 CTAs/SM. act: 0 fp32 out (+resid), 1 leaky fp32, 2 delta-fused,
//               3 leaky + bf16-split out (outhi/outlo).
// ---------------------------------------------------------------------------
#define SMA_LO  20480
#define SM_W    40960
#define SM_BIAS 106496
#define SM_HW2  107008
#define SM_TOT  108544

__global__ __launch_bounds__(256, 2) void gemm_mma(
    const uint32_t* __restrict__ Ahi, const uint32_t* __restrict__ Alo,
    const uint4* __restrict__ fragW,
    const float* __restrict__ bias, const float* __restrict__ resid,
    float* __restrict__ out, int M, int act,
    const float* __restrict__ hw2, const float* __restrict__ hb2,
    float* __restrict__ delta,
    uint32_t* __restrict__ outhi, uint32_t* __restrict__ outlo)
{
    extern __shared__ char sm[];
    uint32_t* sAhi = (uint32_t*)sm;
    uint32_t* sAlo = (uint32_t*)(sm + SMA_LO);
    uint4* sW = (uint4*)(sm + SM_W);
    const int tid = threadIdx.x;

    // Copy W (fragment-major, verbatim) + bias (+ hw2 in delta mode)
#pragma unroll
    for (int i = 0; i < 16; i++)
        sW[tid + i * 256] = fragW[tid + i * 256];
    if (tid < 128) ((float*)(sm + SM_BIAS))[tid] = bias[tid];
    if (act == 2) {
        for (int i = tid; i < 384; i += 256)
            ((float*)(sm + SM_HW2))[i] = hw2[i];
    }

    const int warp = tid >> 5, lane = tid & 31;
    const int g = lane >> 2, q = lane & 3;
    const int r0 = warp * 16;

    float acc[16][4];
#pragma unroll
    for (int ct = 0; ct < 16; ct++)
#pragma unroll
        for (int c = 0; c < 4; c++) acc[ct][c] = 0.f;

    const int srow = tid & 127;
    const int sgrp = (tid >> 7) * 4;          // uint4 seg base 0 or 4
    const int grow = blockIdx.x * 128 + srow;

    for (int half = 0; half < 2; half++) {
        // Stage A half: 128 rows x 32 u32 each of hi/lo, smem row stride 40 u32
        {
            uint4 z4 = make_uint4(0u, 0u, 0u, 0u);
            const uint4* ghf = (grow < M)
                ? (const uint4*)(Ahi + (size_t)grow * 64 + half * 32) : nullptr;
            const uint4* glf = (grow < M)
                ? (const uint4*)(Alo + (size_t)grow * 64 + half * 32) : nullptr;
            uint4* dh = (uint4*)(sAhi + srow * 40);
            uint4* dl = (uint4*)(sAlo + srow * 40);
#pragma unroll
            for (int i = 0; i < 4; i++) {
                dh[sgrp + i] = ghf ? ghf[sgrp + i] : z4;
                dl[sgrp + i] = glf ? glf[sgrp + i] : z4;
            }
        }
        __syncthreads();

#pragma unroll
        for (int kc2 = 0; kc2 < 4; kc2++) {
            const int kc = half * 4 + kc2;
            const int aoff = kc2 * 8 + 2 * q;
            uint2 h0 = *(const uint2*)(sAhi + (r0 + g) * 40 + aoff);
            uint2 h1 = *(const uint2*)(sAhi + (r0 + g + 8) * 40 + aoff);
            uint2 l0 = *(const uint2*)(sAlo + (r0 + g) * 40 + aoff);
            uint2 l1 = *(const uint2*)(sAlo + (r0 + g + 8) * 40 + aoff);
            uint32_t ahi[4] = { h0.x, h1.x, h0.y, h1.y };
            uint32_t alo[4] = { l0.x, l1.x, l0.y, l1.y };

            const uint4* wbase = sW + kc * 32 + g * 4 + q;
#pragma unroll
            for (int ct = 0; ct < 16; ct++) {
                uint4 wv = wbase[ct * 256];
                uint32_t bh[2] = { wv.x, wv.y };
                uint32_t bl[2] = { wv.z, wv.w };
                mma_bf16(acc[ct], ahi, bh);
                mma_bf16(acc[ct], ahi, bl);
                mma_bf16(acc[ct], alo, bh);
            }
        }
        __syncthreads();
    }

    const float* sbias = (const float*)(sm + SM_BIAS);
    int orow0 = blockIdx.x * 128 + r0 + g;
    int orow1 = orow0 + 8;

    if (act == 2) {
        // delta mode: leaky(acc+bias) @ hw2 -> quad-reduce -> tanh
        const float* shw2 = (const float*)(sm + SM_HW2);
        float p0[3] = {0.f, 0.f, 0.f}, p1[3] = {0.f, 0.f, 0.f};
#pragma unroll
        for (int ct = 0; ct < 16; ct++) {
            int col = ct * 8 + q * 2;
            float b0 = sbias[col], b1 = sbias[col + 1];
            float v00 = leaky(acc[ct][0] + b0), v01 = leaky(acc[ct][1] + b1);
            float v10 = leaky(acc[ct][2] + b0), v11 = leaky(acc[ct][3] + b1);
#pragma unroll
            for (int d = 0; d < 3; d++) {
                p0[d] += v00 * shw2[col * 3 + d] + v01 * shw2[(col + 1) * 3 + d];
                p1[d] += v10 * shw2[col * 3 + d] + v11 * shw2[(col + 1) * 3 + d];
            }
        }
#pragma unroll
        for (int d = 0; d < 3; d++) {
            p0[d] += __shfl_xor_sync(0xFFFFFFFFu, p0[d], 1);
            p0[d] += __shfl_xor_sync(0xFFFFFFFFu, p0[d], 2);
            p1[d] += __shfl_xor_sync(0xFFFFFFFFu, p1[d], 1);
            p1[d] += __shfl_xor_sync(0xFFFFFFFFu, p1[d], 2);
        }
        if (q == 0) {
            if (orow0 < M) {
#pragma unroll
                for (int d = 0; d < 3; d++)
                    delta[orow0 * 3 + d] = tanhf(p0[d] + hb2[d]);
            }
            if (orow1 < M) {
#pragma unroll
                for (int d = 0; d < 3; d++)
                    delta[orow1 * 3 + d] = tanhf(p1[d] + hb2[d]);
            }
        }
        return;
    }

    if (act == 3) {
        // leaky + bf16-split output (t for GEMM4)
#pragma unroll
        for (int ct = 0; ct < 16; ct++) {
            int col = ct * 8 + q * 2;
            float b0 = sbias[col], b1 = sbias[col + 1];
            float v00 = leaky(acc[ct][0] + b0), v01 = leaky(acc[ct][1] + b1);
            float v10 = leaky(acc[ct][2] + b0), v11 = leaky(acc[ct][3] + b1);
            int p_out = ct * 4 + q;
            int s_out = (p_out >> 3) * 8 + 2 * (p_out & 3) + ((p_out >> 2) & 1);
            if (orow0 < M) {
                outhi[(size_t)orow0 * 64 + s_out] = pack_hi(v00, v01);
                outlo[(size_t)orow0 * 64 + s_out] = pack_lo(v00, v01);
            }
            if (orow1 < M) {
                outhi[(size_t)orow1 * 64 + s_out] = pack_hi(v10, v11);
                outlo[(size_t)orow1 * 64 + s_out] = pack_lo(v10, v11);
            }
        }
        return;
    }

#pragma unroll
    for (int ct = 0; ct < 16; ct++) {
        int col = ct * 8 + q * 2;
        float b0 = sbias[col], b1 = sbias[col + 1];
        float v00 = acc[ct][0] + b0, v01 = acc[ct][1] + b1;
        float v10 = acc[ct][2] + b0, v11 = acc[ct][3] + b1;
        if (act == 1) {
            v00 = leaky(v00); v01 = leaky(v01);
            v10 = leaky(v10); v11 = leaky(v11);
        }
        if (orow0 < M) {
            if (resid) {
                float2 r = *(const float2*)(resid + (size_t)orow0 * CC + col);
                v00 += r.x; v01 += r.y;
            }
            *(float2*)(out + (size_t)orow0 * CC + col) = make_float2(v00, v01);
        }
        if (orow1 < M) {
            if (resid) {
                float2 r = *(const float2*)(resid + (size_t)orow1 * CC + col);
                v10 += r.x; v11 += r.y;
            }
            *(float2*)(out + (size_t)orow1 * CC + col) = make_float2(v10, v11);
        }
    }
}

__global__ void zero_kernel(float4* __restrict__ p, int n4)
{
    int i = blockIdx.x * blockDim.x + threadIdx.x;
    if (i < n4) p[i] = make_float4(0.f, 0.f, 0.f, 0.f);
}

// ---------------------------------------------------------------------------
// Edge kernel: one warp per edge; scatter-add via red.global.add.v4.f32
// ---------------------------------------------------------------------------
__global__ __launch_bounds__(256) void edge_kernel(
    const void* __restrict__ ei_raw, const float* __restrict__ pos,
    const float* __restrict__ delta, const float* __restrict__ y,
    const float* __restrict__ f_w, float* __restrict__ aggr, int E, int M)
{
    int e = (blockIdx.x * 256 + threadIdx.x) >> 5;
    int lane = threadIdx.x & 31;
    if (e >= E) return;

    int j, i;
    if (g_is64) {
        const long long* ei = (const long long*)ei_raw;
        j = (int)ei[e];
        i = (int)ei[E + e];
    } else {
        const int* ei = (const int*)ei_raw;
        j = ei[e];
        i = ei[E + e];
    }
    if ((unsigned)j >= (unsigned)M || (unsigned)i >= (unsigned)M) return;

    float r0 = pos[j * 3 + 0] - pos[i * 3 + 0] + delta[i * 3 + 0];
    float r1 = pos[j * 3 + 1] - pos[i * 3 + 1] + delta[i * 3 + 1];
    float r2 = pos[j * 3 + 2] - pos[i * 3 + 2] + delta[i * 3 + 2];

    int c = lane * 4;
    float4 yv = *(const float4*)(y + (size_t)j * CC + c);
    float4 w0 = *(const float4*)(f_w + 0 * CC + c);
    float4 w1 = *(const float4*)(f_w + 1 * CC + c);
    float4 w2 = *(const float4*)(f_w + 2 * CC + c);

    float4 z;
    z.x = leaky(yv.x + r0 * w0.x + r1 * w1.x + r2 * w2.x);
    z.y = leaky(yv.y + r0 * w0.y + r1 * w1.y + r2 * w2.y);
    z.z = leaky(yv.z + r0 * w0.z + r1 * w1.z + r2 * w2.z);
    z.w = leaky(yv.w + r0 * w0.w + r1 * w1.w + r2 * w2.w);

    float* dst = aggr + (size_t)i * CC + c;
    asm volatile("red.global.add.v4.f32 [%0], {%1,%2,%3,%4};"
                 :: "l"(dst), "f"(z.x), "f"(z.y), "f"(z.z), "f"(z.w)
                 : "memory");
}

// ---------------------------------------------------------------------------
extern "C" void kernel_launch(void* const* d_in, const int* in_sizes, int n_in,
                              void* d_out, int out_size)
{
    const float* x      = (const float*)d_in[0];
    const float* pos    = (const float*)d_in[1];
    const void*  ei     = d_in[2];
    const float* h_w1   = (const float*)d_in[3];
    const float* h_b1   = (const float*)d_in[4];
    const float* h_w2   = (const float*)d_in[5];
    const float* h_b2   = (const float*)d_in[6];
    const float* f_w    = (const float*)d_in[7];
    const float* f_b    = (const float*)d_in[8];
    const float* g_w1   = (const float*)d_in[9];
    const float* g_b1   = (const float*)d_in[10];
    const float* g_w2   = (const float*)d_in[11];
    const float* g_b2   = (const float*)d_in[12];
    float* out = (float*)d_out;

    const int M = in_sizes[0] / CC;  // 50000
    const int E = in_sizes[2] / 2;   // 800000

    float *y, *aggr, *delta;
    uint4* fragW;
    uint32_t *xhi, *xlo, *ahi, *alo, *thi, *tlo;
    cudaGetSymbolAddress((void**)&y,     g_y);
    cudaGetSymbolAddress((void**)&aggr,  g_aggr);
    cudaGetSymbolAddress((void**)&delta, g_delta);
    cudaGetSymbolAddress((void**)&fragW, g_fragW);
    cudaGetSymbolAddress((void**)&xhi,   g_xhi);
    cudaGetSymbolAddress((void**)&xlo,   g_xlo);
    cudaGetSymbolAddress((void**)&ahi,   g_ahi);
    cudaGetSymbolAddress((void**)&alo,   g_alo);
    cudaGetSymbolAddress((void**)&thi,   g_thi);
    cudaGetSymbolAddress((void**)&tlo,   g_tlo);

    static int smem_set = 0;
    if (!smem_set) {
        cudaFuncSetAttribute(gemm_mma, cudaFuncAttributeMaxDynamicSharedMemorySize, SM_TOT);
        smem_set = 1;
    }

    const int gcta = (M + 127) / 128;
    const int ccta = (M * 64 + 255) / 256;

    // --- prep ---
    detect_dtype_kernel<<<1, 32>>>((const int*)ei, 2048);
    prep_weights_kernel<<<(4 * 4096 + 255) / 256, 256>>>(h_w1, f_w + 3 * CC, g_w1, g_w2);
    zero_kernel<<<(M * CC / 4 + 255) / 256, 256>>>((float4*)aggr, M * CC / 4);
    cvt_split_kernel<<<ccta, 256>>>(x, xhi, xlo, M * 64);

    // --- GEMMs + delta ---
    // delta = tanh(leaky(x @ h_w1 + h_b1) @ h_w2 + h_b2)  (fused)
    gemm_mma<<<gcta, 256, SM_TOT>>>(xhi, xlo, fragW + 0 * 4096, h_b1, nullptr,
                                    nullptr, M, 2, h_w2, h_b2, delta, nullptr, nullptr);
    // y = x @ f_w[3:, :] + f_b
    gemm_mma<<<gcta, 256, SM_TOT>>>(xhi, xlo, fragW + 1 * 4096, f_b, nullptr,
                                    y, M, 0, nullptr, nullptr, nullptr, nullptr, nullptr);

    // --- aggregation via atomics ---
    edge_kernel<<<(E + 7) / 8, 256>>>(ei, pos, delta, y, f_w, aggr, E, M);
    cvt_split_kernel<<<ccta, 256>>>(aggr, ahi, alo, M * 64);

    // t = leaky(aggr @ g_w1 + g_b1)   (bf16-split output)
    gemm_mma<<<gcta, 256, SM_TOT>>>(ahi, alo, fragW + 2 * 4096, g_b1, nullptr,
                                    nullptr, M, 3, nullptr, nullptr, nullptr, thi, tlo);
    // out = t @ g_w2 + g_b2 + x
    gemm_mma<<<gcta, 256, SM_TOT>>>(thi, tlo, fragW + 3 * 4096, g_b2, x,
                                    out, M, 0, nullptr, nullptr, nullptr, nullptr, nullptr);
}

// round 9
// speedup vs baseline: 1.0313x; 1.0313x over previous
#include <cuda_runtime.h>
#include <cuda_bf16.h>
#include <cstdint>

#define NN 50000
#define EE 800000
#define CC 128
#define NEG 0.01f

// Scratch (no allocation allowed -> __device__ globals)
__device__ float g_y[NN * CC];
__device__ float g_t[NN * CC];
__device__ float g_aggr[NN * CC];
__device__ float g_delta[NN * 3];
__device__ int   g_is64;
// Fragment-major weights: per matrix 4096 x uint4 {bhi0,bhi1,blo0,blo1} = 64KB
// index (per matrix): ct*256 + kc*32 + g*4 + q
__device__ uint4 g_fragW[4 * 4096];

__device__ __forceinline__ float leaky(float v) {
    return v >= 0.0f ? v : NEG * v;
}

// ---------------------------------------------------------------------------
__global__ void detect_dtype_kernel(const int* __restrict__ ei32, int n_words)
{
    if (blockIdx.x == 0 && threadIdx.x == 0) {
        int all_hi_zero = 1;
        int pairs = n_words / 2;
        if (pairs > 1024) pairs = 1024;
        for (int p = 0; p < pairs; ++p) {
            if (ei32[2 * p + 1] != 0) { all_hi_zero = 0; break; }
        }
        g_is64 = all_hi_zero;
    }
}

// ---------------------------------------------------------------------------
__device__ __forceinline__ uint32_t pack_hi(float a, float b) {
    __nv_bfloat16 ha = __float2bfloat16(a), hb = __float2bfloat16(b);
    return (uint32_t)__bfloat16_as_ushort(ha) | ((uint32_t)__bfloat16_as_ushort(hb) << 16);
}
__device__ __forceinline__ uint32_t pack_lo(float a, float b) {
    __nv_bfloat16 ha = __float2bfloat16(a), hb = __float2bfloat16(b);
    __nv_bfloat16 la = __float2bfloat16(a - __bfloat162float(ha));
    __nv_bfloat16 lb = __float2bfloat16(b - __bfloat162float(hb));
    return (uint32_t)__bfloat16_as_ushort(la) | ((uint32_t)__bfloat16_as_ushort(lb) << 16);
}

__global__ void prep_weights_kernel(const float* __restrict__ w0,
                                    const float* __restrict__ w1,
                                    const float* __restrict__ w2,
                                    const float* __restrict__ w3)
{
    int idx = blockIdx.x * 256 + threadIdx.x;   // 4*4096 entries
    if (idx >= 4 * 4096) return;
    int m = idx >> 12;
    int rem = idx & 4095;
    int col = rem >> 5;        // 0..127
    int kc  = (rem >> 2) & 7;  // 0..7
    int q   = rem & 3;         // 0..3
    const float* w = (m == 0) ? w0 : (m == 1) ? w1 : (m == 2) ? w2 : w3;
    int k0 = kc * 16 + 2 * q;
    float a0 = w[(k0 + 0) * CC + col];
    float a1 = w[(k0 + 1) * CC + col];
    float a2 = w[(k0 + 8) * CC + col];
    float a3 = w[(k0 + 9) * CC + col];
    uint4 v;
    v.x = pack_hi(a0, a1);
    v.y = pack_hi(a2, a3);
    v.z = pack_lo(a0, a1);
    v.w = pack_lo(a2, a3);
    int ct = col >> 3, g = col & 7;
    g_fragW[m * 4096 + ct * 256 + kc * 32 + g * 4 + q] = v;
}

// ---------------------------------------------------------------------------
__device__ __forceinline__ void mma_bf16(float* c, const uint32_t* a, const uint32_t* b)
{
    asm volatile(
        "mma.sync.aligned.m16n8k16.row.col.f32.bf16.bf16.f32 "
        "{%0,%1,%2,%3}, {%4,%5,%6,%7}, {%8,%9}, {%0,%1,%2,%3};"
        : "+f"(c[0]), "+f"(c[1]), "+f"(c[2]), "+f"(c[3])
        : "r"(a[0]), "r"(a[1]), "r"(a[2]), "r"(a[3]), "r"(b[0]), "r"(b[1]));
}

// ---------------------------------------------------------------------------
// Split-bf16 GEMM. Warp tile 32x64 (4 m-groups x 2 n-groups) -> W LDS halved.
// A converted fp32->bf16 hi/lo during smem STAGING (once per element).
// smem layout (fragment-pair, per half of K):
//   sAhi [128][40]u32 (32 data + 8 pad), sAlo same, sW 64KB, bias, hw2.
// Fragment-pair index: s = kc2*8 + 2q + j holds cols {2p,2p+1}, p = kc2*8+q+4j.
// act: 0 fp32 out (+resid), 1 leaky fp32, 2 delta-fused.
// ---------------------------------------------------------------------------
#define SMA_LO  20480
#define SM_W    40960
#define SM_BIAS 106496
#define SM_HW2  107008
#define SM_TOT  108544

__global__ __launch_bounds__(256, 2) void gemm_mma(
    const float* __restrict__ A, const uint4* __restrict__ fragW,
    const float* __restrict__ bias, const float* __restrict__ resid,
    float* __restrict__ out, int M, int act,
    const float* __restrict__ hw2, const float* __restrict__ hb2,
    float* __restrict__ delta)
{
    extern __shared__ char sm[];
    uint32_t* sAhi = (uint32_t*)sm;
    uint32_t* sAlo = (uint32_t*)(sm + SMA_LO);
    uint4* sW = (uint4*)(sm + SM_W);
    const int tid = threadIdx.x;

    // Copy W (fragment-major, verbatim) + bias (+ hw2 in delta mode)
#pragma unroll
    for (int i = 0; i < 16; i++)
        sW[tid + i * 256] = fragW[tid + i * 256];
    if (tid < 128) ((float*)(sm + SM_BIAS))[tid] = bias[tid];
    if (act == 2) {
        for (int i = tid; i < 384; i += 256)
            ((float*)(sm + SM_HW2))[i] = hw2[i];
    }

    const int warp = tid >> 5, lane = tid & 31;
    const int g = lane >> 2, q = lane & 3;
    const int warp_m = warp >> 1, warp_n = warp & 1;
    const int rb = warp_m * 32;

    float acc[2][8][4];
#pragma unroll
    for (int t = 0; t < 2; t++)
#pragma unroll
        for (int ct = 0; ct < 8; ct++)
#pragma unroll
            for (int c = 0; c < 4; c++) acc[t][ct][c] = 0.f;

    const int srow = tid & 127;
    const int sseg = (tid >> 7) * 8;          // float4 seg base 0 or 8 (of 16)
    const int grow = blockIdx.x * 128 + srow;

    for (int half = 0; half < 2; half++) {
        // Stage A half [128 x 64] with fp32->bf16 hi/lo split, frag-pair layout
        {
            const float4* src = (grow < M)
                ? (const float4*)(A + (size_t)grow * CC + half * 64) : nullptr;
            uint32_t* dh = sAhi + srow * 40;
            uint32_t* dl = sAlo + srow * 40;
#pragma unroll
            for (int i = 0; i < 8; i++) {
                float4 v = src ? src[sseg + i] : make_float4(0.f, 0.f, 0.f, 0.f);
                int p0 = (sseg + i) * 2, p1 = p0 + 1;
                int o0 = p0 & 7, o1 = p1 & 7;
                int s0 = (p0 >> 3) * 8 + 2 * (o0 & 3) + (o0 >> 2);
                int s1 = (p1 >> 3) * 8 + 2 * (o1 & 3) + (o1 >> 2);
                dh[s0] = pack_hi(v.x, v.y);
                dl[s0] = pack_lo(v.x, v.y);
                dh[s1] = pack_hi(v.z, v.w);
                dl[s1] = pack_lo(v.z, v.w);
            }
        }
        __syncthreads();

#pragma unroll
        for (int kc2 = 0; kc2 < 4; kc2++) {
            const int kc = half * 4 + kc2;
            const int aoff = kc2 * 8 + 2 * q;
            uint32_t ahi[2][4], alo[2][4];
#pragma unroll
            for (int t = 0; t < 2; t++) {
                int rowA = rb + 16 * t + g;
                uint2 h0 = *(const uint2*)(sAhi + rowA * 40 + aoff);
                uint2 h1 = *(const uint2*)(sAhi + (rowA + 8) * 40 + aoff);
                uint2 l0 = *(const uint2*)(sAlo + rowA * 40 + aoff);
                uint2 l1 = *(const uint2*)(sAlo + (rowA + 8) * 40 + aoff);
                ahi[t][0] = h0.x; ahi[t][1] = h1.x; ahi[t][2] = h0.y; ahi[t][3] = h1.y;
                alo[t][0] = l0.x; alo[t][1] = l1.x; alo[t][2] = l0.y; alo[t][3] = l1.y;
            }

            const uint4* wbase = sW + kc * 32 + g * 4 + q;
#pragma unroll
            for (int ct = 0; ct < 8; ct++) {
                uint4 wv = wbase[(warp_n * 8 + ct) * 256];
                uint32_t bh[2] = { wv.x, wv.y };
                uint32_t bl[2] = { wv.z, wv.w };
#pragma unroll
                for (int t = 0; t < 2; t++) {
                    mma_bf16(acc[t][ct], ahi[t], bh);
                    mma_bf16(acc[t][ct], ahi[t], bl);
                    mma_bf16(acc[t][ct], alo[t], bh);
                }
            }
        }
        __syncthreads();
    }

    const float* sbias = (const float*)(sm + SM_BIAS);

    if (act == 2) {
        // delta: leaky(acc+bias) @ hw2, quad-reduce, cross-warp_n sum via smem
        const float* shw2 = (const float*)(sm + SM_HW2);
        float* sPart = (float*)(sm + SM_W);   // [2][128][3] floats (W done)
        float p[2][2][3];
#pragma unroll
        for (int t = 0; t < 2; t++)
#pragma unroll
            for (int h = 0; h < 2; h++)
#pragma unroll
                for (int d = 0; d < 3; d++) p[t][h][d] = 0.f;
#pragma unroll
        for (int ct = 0; ct < 8; ct++) {
            int col = (warp_n * 8 + ct) * 8 + q * 2;
            float b0 = sbias[col], b1 = sbias[col + 1];
#pragma unroll
            for (int t = 0; t < 2; t++) {
                float v0 = leaky(acc[t][ct][0] + b0), v1 = leaky(acc[t][ct][1] + b1);
                float v2 = leaky(acc[t][ct][2] + b0), v3 = leaky(acc[t][ct][3] + b1);
#pragma unroll
                for (int d = 0; d < 3; d++) {
                    p[t][0][d] += v0 * shw2[col * 3 + d] + v1 * shw2[(col + 1) * 3 + d];
                    p[t][1][d] += v2 * shw2[col * 3 + d] + v3 * shw2[(col + 1) * 3 + d];
                }
            }
        }
#pragma unroll
        for (int t = 0; t < 2; t++)
#pragma unroll
            for (int h = 0; h < 2; h++)
#pragma unroll
                for (int d = 0; d < 3; d++) {
                    p[t][h][d] += __shfl_xor_sync(0xFFFFFFFFu, p[t][h][d], 1);
                    p[t][h][d] += __shfl_xor_sync(0xFFFFFFFFu, p[t][h][d], 2);
                }
        if (q == 0) {
#pragma unroll
            for (int t = 0; t < 2; t++)
#pragma unroll
                for (int h = 0; h < 2; h++) {
                    int row = rb + 16 * t + 8 * h + g;
#pragma unroll
                    for (int d = 0; d < 3; d++)
                        sPart[(warp_n * 128 + row) * 3 + d] = p[t][h][d];
                }
        }
        __syncthreads();
        if (tid < 128) {
            int orow = blockIdx.x * 128 + tid;
            if (orow < M) {
#pragma unroll
                for (int d = 0; d < 3; d++)
                    delta[orow * 3 + d] = tanhf(sPart[tid * 3 + d] +
                                                sPart[(128 + tid) * 3 + d] + hb2[d]);
            }
        }
        return;
    }

#pragma unroll
    for (int t = 0; t < 2; t++) {
        int orow0 = blockIdx.x * 128 + rb + 16 * t + g;
        int orow1 = orow0 + 8;
#pragma unroll
        for (int ct = 0; ct < 8; ct++) {
            int col = (warp_n * 8 + ct) * 8 + q * 2;
            float b0 = sbias[col], b1 = sbias[col + 1];
            float v00 = acc[t][ct][0] + b0, v01 = acc[t][ct][1] + b1;
            float v10 = acc[t][ct][2] + b0, v11 = acc[t][ct][3] + b1;
            if (act == 1) {
                v00 = leaky(v00); v01 = leaky(v01);
                v10 = leaky(v10); v11 = leaky(v11);
            }
            if (orow0 < M) {
                if (resid) {
                    float2 r = *(const float2*)(resid + (size_t)orow0 * CC + col);
                    v00 += r.x; v01 += r.y;
                }
                *(float2*)(out + (size_t)orow0 * CC + col) = make_float2(v00, v01);
            }
            if (orow1 < M) {
                if (resid) {
                    float2 r = *(const float2*)(resid + (size_t)orow1 * CC + col);
                    v10 += r.x; v11 += r.y;
                }
                *(float2*)(out + (size_t)orow1 * CC + col) = make_float2(v10, v11);
            }
        }
    }
}

__global__ void zero_kernel(float4* __restrict__ p, int n4)
{
    int i = blockIdx.x * blockDim.x + threadIdx.x;
    if (i < n4) p[i] = make_float4(0.f, 0.f, 0.f, 0.f);
}

// ---------------------------------------------------------------------------
// Edge kernel: one warp per edge; scatter-add via red.global.add.v4.f32
// ---------------------------------------------------------------------------
__global__ __launch_bounds__(256) void edge_kernel(
    const void* __restrict__ ei_raw, const float* __restrict__ pos,
    const float* __restrict__ delta, const float* __restrict__ y,
    const float* __restrict__ f_w, float* __restrict__ aggr, int E, int M)
{
    int e = (blockIdx.x * 256 + threadIdx.x) >> 5;
    int lane = threadIdx.x & 31;
    if (e >= E) return;

    int j, i;
    if (g_is64) {
        const long long* ei = (const long long*)ei_raw;
        j = (int)ei[e];
        i = (int)ei[E + e];
    } else {
        const int* ei = (const int*)ei_raw;
        j = ei[e];
        i = ei[E + e];
    }
    if ((unsigned)j >= (unsigned)M || (unsigned)i >= (unsigned)M) return;

    float r0 = pos[j * 3 + 0] - pos[i * 3 + 0] + delta[i * 3 + 0];
    float r1 = pos[j * 3 + 1] - pos[i * 3 + 1] + delta[i * 3 + 1];
    float r2 = pos[j * 3 + 2] - pos[i * 3 + 2] + delta[i * 3 + 2];

    int c = lane * 4;
    float4 yv = *(const float4*)(y + (size_t)j * CC + c);
    float4 w0 = *(const float4*)(f_w + 0 * CC + c);
    float4 w1 = *(const float4*)(f_w + 1 * CC + c);
    float4 w2 = *(const float4*)(f_w + 2 * CC + c);

    float4 z;
    z.x = leaky(yv.x + r0 * w0.x + r1 * w1.x + r2 * w2.x);
    z.y = leaky(yv.y + r0 * w0.y + r1 * w1.y + r2 * w2.y);
    z.z = leaky(yv.z + r0 * w0.z + r1 * w1.z + r2 * w2.z);
    z.w = leaky(yv.w + r0 * w0.w + r1 * w1.w + r2 * w2.w);

    float* dst = aggr + (size_t)i * CC + c;
    asm volatile("red.global.add.v4.f32 [%0], {%1,%2,%3,%4};"
                 :: "l"(dst), "f"(z.x), "f"(z.y), "f"(z.z), "f"(z.w)
                 : "memory");
}

// ---------------------------------------------------------------------------
extern "C" void kernel_launch(void* const* d_in, const int* in_sizes, int n_in,
                              void* d_out, int out_size)
{
    const float* x      = (const float*)d_in[0];
    const float* pos    = (const float*)d_in[1];
    const void*  ei     = d_in[2];
    const float* h_w1   = (const float*)d_in[3];
    const float* h_b1   = (const float*)d_in[4];
    const float* h_w2   = (const float*)d_in[5];
    const float* h_b2   = (const float*)d_in[6];
    const float* f_w    = (const float*)d_in[7];
    const float* f_b    = (const float*)d_in[8];
    const float* g_w1   = (const float*)d_in[9];
    const float* g_b1   = (const float*)d_in[10];
    const float* g_w2   = (const float*)d_in[11];
    const float* g_b2   = (const float*)d_in[12];
    float* out = (float*)d_out;

    const int M = in_sizes[0] / CC;  // 50000
    const int E = in_sizes[2] / 2;   // 800000

    float *y, *t, *aggr, *delta;
    uint4* fragW;
    cudaGetSymbolAddress((void**)&y,     g_y);
    cudaGetSymbolAddress((void**)&t,     g_t);
    cudaGetSymbolAddress((void**)&aggr,  g_aggr);
    cudaGetSymbolAddress((void**)&delta, g_delta);
    cudaGetSymbolAddress((void**)&fragW, g_fragW);

    static int smem_set = 0;
    if (!smem_set) {
        cudaFuncSetAttribute(gemm_mma, cudaFuncAttributeMaxDynamicSharedMemorySize, SM_TOT);
        smem_set = 1;
    }

    const int gcta = (M + 127) / 128;

    // --- prep ---
    detect_dtype_kernel<<<1, 32>>>((const int*)ei, 2048);
    prep_weights_kernel<<<(4 * 4096 + 255) / 256, 256>>>(h_w1, f_w + 3 * CC, g_w1, g_w2);
    zero_kernel<<<(M * CC / 4 + 255) / 256, 256>>>((float4*)aggr, M * CC / 4);

    // --- GEMMs + delta ---
    // delta = tanh(leaky(x @ h_w1 + h_b1) @ h_w2 + h_b2)  (fused, hidden never stored)
    gemm_mma<<<gcta, 256, SM_TOT>>>(x, fragW + 0 * 4096, h_b1, nullptr, nullptr, M, 2,
                                    h_w2, h_b2, delta);
    // y = x @ f_w[3:, :] + f_b
    gemm_mma<<<gcta, 256, SM_TOT>>>(x, fragW + 1 * 4096, f_b, nullptr, y, M, 0,
                                    nullptr, nullptr, nullptr);

    // --- aggregation via atomics ---
    edge_kernel<<<(E + 7) / 8, 256>>>(ei, pos, delta, y, f_w, aggr, E, M);

    // t = leaky(aggr @ g_w1 + g_b1)
    gemm_mma<<<gcta, 256, SM_TOT>>>(aggr, fragW + 2 * 4096, g_b1, nullptr, t, M, 1,
                                    nullptr, nullptr, nullptr);
    // out = t @ g_w2 + g_b2 + x
    gemm_mma<<<gcta, 256, SM_TOT>>>(t, fragW + 3 * 4096, g_b2, x, out, M, 0,
                                    nullptr, nullptr, nullptr);
}

// round 10
// speedup vs baseline: 1.1007x; 1.0673x over previous
#include <cuda_runtime.h>
#include <cuda_bf16.h>
#include <cstdint>

#define NN 50000
#define EE 800000
#define CC 128
#define NEG 0.01f

// Scratch (no allocation allowed -> __device__ globals)
__device__ float g_y[NN * CC];
__device__ float g_t[NN * CC];
__device__ float g_aggr[NN * CC];
__device__ float g_delta[NN * 3];
__device__ int   g_is64;
// Fragment-major weights: per matrix 4096 x uint4 {bhi0,bhi1,blo0,blo1} = 64KB
// index (per matrix): ct*256 + kc*32 + g*4 + q
__device__ uint4 g_fragW[4 * 4096];

__device__ __forceinline__ float leaky(float v) {
    return v >= 0.0f ? v : NEG * v;
}

// ---------------------------------------------------------------------------
__global__ void detect_dtype_kernel(const int* __restrict__ ei32, int n_words)
{
    if (blockIdx.x == 0 && threadIdx.x == 0) {
        int all_hi_zero = 1;
        int pairs = n_words / 2;
        if (pairs > 1024) pairs = 1024;
        for (int p = 0; p < pairs; ++p) {
            if (ei32[2 * p + 1] != 0) { all_hi_zero = 0; break; }
        }
        g_is64 = all_hi_zero;
    }
}

// ---------------------------------------------------------------------------
__device__ __forceinline__ uint32_t pack_hi(float a, float b) {
    __nv_bfloat16 ha = __float2bfloat16(a), hb = __float2bfloat16(b);
    return (uint32_t)__bfloat16_as_ushort(ha) | ((uint32_t)__bfloat16_as_ushort(hb) << 16);
}
__device__ __forceinline__ uint32_t pack_lo(float a, float b) {
    __nv_bfloat16 ha = __float2bfloat16(a), hb = __float2bfloat16(b);
    __nv_bfloat16 la = __float2bfloat16(a - __bfloat162float(ha));
    __nv_bfloat16 lb = __float2bfloat16(b - __bfloat162float(hb));
    return (uint32_t)__bfloat16_as_ushort(la) | ((uint32_t)__bfloat16_as_ushort(lb) << 16);
}

__global__ void prep_weights_kernel(const float* __restrict__ w0,
                                    const float* __restrict__ w1,
                                    const float* __restrict__ w2,
                                    const float* __restrict__ w3)
{
    int idx = blockIdx.x * 256 + threadIdx.x;   // 4*4096 entries
    if (idx >= 4 * 4096) return;
    int m = idx >> 12;
    int rem = idx & 4095;
    int col = rem >> 5;        // 0..127
    int kc  = (rem >> 2) & 7;  // 0..7
    int q   = rem & 3;         // 0..3
    const float* w = (m == 0) ? w0 : (m == 1) ? w1 : (m == 2) ? w2 : w3;
    int k0 = kc * 16 + 2 * q;
    float a0 = w[(k0 + 0) * CC + col];
    float a1 = w[(k0 + 1) * CC + col];
    float a2 = w[(k0 + 8) * CC + col];
    float a3 = w[(k0 + 9) * CC + col];
    uint4 v;
    v.x = pack_hi(a0, a1);
    v.y = pack_hi(a2, a3);
    v.z = pack_lo(a0, a1);
    v.w = pack_lo(a2, a3);
    int ct = col >> 3, g = col & 7;
    g_fragW[m * 4096 + ct * 256 + kc * 32 + g * 4 + q] = v;
}

// ---------------------------------------------------------------------------
__device__ __forceinline__ void mma_bf16(float* c, const uint32_t* a, const uint32_t* b)
{
    asm volatile(
        "mma.sync.aligned.m16n8k16.row.col.f32.bf16.bf16.f32 "
        "{%0,%1,%2,%3}, {%4,%5,%6,%7}, {%8,%9}, {%0,%1,%2,%3};"
        : "+f"(c[0]), "+f"(c[1]), "+f"(c[2]), "+f"(c[3])
        : "r"(a[0]), "r"(a[1]), "r"(a[2]), "r"(a[3]), "r"(b[0]), "r"(b[1]));
}

__device__ __forceinline__ void cvt_hilo(float2 f, uint32_t& hi, uint32_t& lo)
{
    __nv_bfloat16 hx = __float2bfloat16(f.x);
    __nv_bfloat16 hy = __float2bfloat16(f.y);
    __nv_bfloat16 lx = __float2bfloat16(f.x - __bfloat162float(hx));
    __nv_bfloat16 ly = __float2bfloat16(f.y - __bfloat162float(hy));
    hi = (uint32_t)__bfloat16_as_ushort(hx) | ((uint32_t)__bfloat16_as_ushort(hy) << 16);
    lo = (uint32_t)__bfloat16_as_ushort(lx) | ((uint32_t)__bfloat16_as_ushort(ly) << 16);
}

// ---------------------------------------------------------------------------
// Split-bf16 GEMM, 512 threads / 16 warps, warp tile 16x64
// (warp_m = warp>>1 -> rows, warp_n = warp&1 -> col half).
// W in smem fragment-major; A staged fp32 in 2 K-chunks of 64 cols (stride 72).
// 2 CTAs/SM -> 32 warps/SM. act: 0 none(+resid), 1 leaky, 2 delta-fused.
// smem: A [0, 36864); W [36864, 102400); bias [102400,+512); hw2 [102912,+1536)
// ---------------------------------------------------------------------------
#define SM_W    36864
#define SM_BIAS 102400
#define SM_HW2  102912
#define SM_TOT  104448

__global__ __launch_bounds__(512, 2) void gemm_mma(
    const float* __restrict__ A, const uint4* __restrict__ fragW,
    const float* __restrict__ bias, const float* __restrict__ resid,
    float* __restrict__ out, int M, int act,
    const float* __restrict__ hw2, const float* __restrict__ hb2,
    float* __restrict__ delta)
{
    extern __shared__ char sm[];
    float* sA = (float*)sm;                       // [128][72]
    uint4* sW = (uint4*)(sm + SM_W);              // 4096 uint4
    const int tid = threadIdx.x;

    // Copy W (fragment-major, verbatim) + bias (+ hw2 in delta mode)
#pragma unroll
    for (int i = 0; i < 8; i++)
        sW[tid + i * 512] = fragW[tid + i * 512];
    if (tid < 128) ((float*)(sm + SM_BIAS))[tid] = bias[tid];
    if (act == 2) {
        for (int i = tid; i < 384; i += 512)
            ((float*)(sm + SM_HW2))[i] = hw2[i];
    }

    const int warp = tid >> 5, lane = tid & 31;
    const int g = lane >> 2, q = lane & 3;
    const int warp_m = warp >> 1, warp_n = warp & 1;
    const int r0 = warp_m * 16;

    float acc[8][4];
#pragma unroll
    for (int ct = 0; ct < 8; ct++)
#pragma unroll
        for (int c = 0; c < 4; c++) acc[ct][c] = 0.f;

    const int srow = tid & 127;
    const int sseg = (tid >> 7) * 4;          // float4 seg base 0,4,8,12
    const int grow = blockIdx.x * 128 + srow;
    const float* a0base = sA + (r0 + g) * 72;
    const float* a1base = sA + (r0 + g + 8) * 72;

    for (int half = 0; half < 2; half++) {
        // Stage A chunk [128 rows x 64 cols] fp32, row stride 72
        {
            const float4* src = (grow < M)
                ? (const float4*)(A + (size_t)grow * CC + half * 64) : nullptr;
            float* dst = sA + srow * 72;
#pragma unroll
            for (int i = 0; i < 4; i++) {
                float4 v = src ? src[sseg + i] : make_float4(0.f, 0.f, 0.f, 0.f);
                *(float4*)(dst + (sseg + i) * 4) = v;
            }
        }
        __syncthreads();

#pragma unroll
        for (int kc2 = 0; kc2 < 4; kc2++) {
            const int kc = half * 4 + kc2;
            const int k0 = kc2 * 16 + q * 2;
            float2 f00 = *(const float2*)(a0base + k0);
            float2 f10 = *(const float2*)(a1base + k0);
            float2 f01 = *(const float2*)(a0base + k0 + 8);
            float2 f11 = *(const float2*)(a1base + k0 + 8);
            uint32_t ahi[4], alo[4];
            cvt_hilo(f00, ahi[0], alo[0]);
            cvt_hilo(f10, ahi[1], alo[1]);
            cvt_hilo(f01, ahi[2], alo[2]);
            cvt_hilo(f11, ahi[3], alo[3]);

            const uint4* wbase = sW + kc * 32 + g * 4 + q;
#pragma unroll
            for (int ct = 0; ct < 8; ct++) {
                uint4 wv = wbase[(warp_n * 8 + ct) * 256];
                uint32_t bh[2] = { wv.x, wv.y };
                uint32_t bl[2] = { wv.z, wv.w };
                mma_bf16(acc[ct], ahi, bh);
                mma_bf16(acc[ct], ahi, bl);
                mma_bf16(acc[ct], alo, bh);
            }
        }
        __syncthreads();
    }

    const float* sbias = (const float*)(sm + SM_BIAS);
    int orow0 = blockIdx.x * 128 + r0 + g;
    int orow1 = orow0 + 8;

    if (act == 2) {
        // delta: leaky(acc+bias) @ hw2, quad-reduce, cross-warp_n sum via smem
        const float* shw2 = (const float*)(sm + SM_HW2);
        float* sPart = (float*)(sm + SM_W);   // [2][128][3] floats (W dead)
        float p0[3] = {0.f, 0.f, 0.f}, p1[3] = {0.f, 0.f, 0.f};
#pragma unroll
        for (int ct = 0; ct < 8; ct++) {
            int col = (warp_n * 8 + ct) * 8 + q * 2;
            float b0 = sbias[col], b1 = sbias[col + 1];
            float v00 = leaky(acc[ct][0] + b0), v01 = leaky(acc[ct][1] + b1);
            float v10 = leaky(acc[ct][2] + b0), v11 = leaky(acc[ct][3] + b1);
#pragma unroll
            for (int d = 0; d < 3; d++) {
                p0[d] += v00 * shw2[col * 3 + d] + v01 * shw2[(col + 1) * 3 + d];
                p1[d] += v10 * shw2[col * 3 + d] + v11 * shw2[(col + 1) * 3 + d];
            }
        }
#pragma unroll
        for (int d = 0; d < 3; d++) {
            p0[d] += __shfl_xor_sync(0xFFFFFFFFu, p0[d], 1);
            p0[d] += __shfl_xor_sync(0xFFFFFFFFu, p0[d], 2);
            p1[d] += __shfl_xor_sync(0xFFFFFFFFu, p1[d], 1);
            p1[d] += __shfl_xor_sync(0xFFFFFFFFu, p1[d], 2);
        }
        if (q == 0) {
            int row0 = r0 + g, row1 = row0 + 8;
#pragma unroll
            for (int d = 0; d < 3; d++) {
                sPart[(warp_n * 128 + row0) * 3 + d] = p0[d];
                sPart[(warp_n * 128 + row1) * 3 + d] = p1[d];
            }
        }
        __syncthreads();
        if (tid < 128) {
            int orow = blockIdx.x * 128 + tid;
            if (orow < M) {
#pragma unroll
                for (int d = 0; d < 3; d++)
                    delta[orow * 3 + d] = tanhf(sPart[tid * 3 + d] +
                                                sPart[(128 + tid) * 3 + d] + hb2[d]);
            }
        }
        return;
    }

#pragma unroll
    for (int ct = 0; ct < 8; ct++) {
        int col = (warp_n * 8 + ct) * 8 + q * 2;
        float b0 = sbias[col], b1 = sbias[col + 1];
        float v00 = acc[ct][0] + b0, v01 = acc[ct][1] + b1;
        float v10 = acc[ct][2] + b0, v11 = acc[ct][3] + b1;
        if (act == 1) {
            v00 = leaky(v00); v01 = leaky(v01);
            v10 = leaky(v10); v11 = leaky(v11);
        }
        if (orow0 < M) {
            if (resid) {
                float2 r = *(const float2*)(resid + (size_t)orow0 * CC + col);
                v00 += r.x; v01 += r.y;
            }
            *(float2*)(out + (size_t)orow0 * CC + col) = make_float2(v00, v01);
        }
        if (orow1 < M) {
            if (resid) {
                float2 r = *(const float2*)(resid + (size_t)orow1 * CC + col);
                v10 += r.x; v11 += r.y;
            }
            *(float2*)(out + (size_t)orow1 * CC + col) = make_float2(v10, v11);
        }
    }
}

__global__ void zero_kernel(float4* __restrict__ p, int n4)
{
    int i = blockIdx.x * blockDim.x + threadIdx.x;
    if (i < n4) p[i] = make_float4(0.f, 0.f, 0.f, 0.f);
}

// ---------------------------------------------------------------------------
// Edge kernel: one warp per edge; scatter-add via red.global.add.v4.f32
// ---------------------------------------------------------------------------
__global__ __launch_bounds__(256) void edge_kernel(
    const void* __restrict__ ei_raw, const float* __restrict__ pos,
    const float* __restrict__ delta, const float* __restrict__ y,
    const float* __restrict__ f_w, float* __restrict__ aggr, int E, int M)
{
    int e = (blockIdx.x * 256 + threadIdx.x) >> 5;
    int lane = threadIdx.x & 31;
    if (e >= E) return;

    int j, i;
    if (g_is64) {
        const long long* ei = (const long long*)ei_raw;
        j = (int)ei[e];
        i = (int)ei[E + e];
    } else {
        const int* ei = (const int*)ei_raw;
        j = ei[e];
        i = ei[E + e];
    }
    if ((unsigned)j >= (unsigned)M || (unsigned)i >= (unsigned)M) return;

    float r0 = pos[j * 3 + 0] - pos[i * 3 + 0] + delta[i * 3 + 0];
    float r1 = pos[j * 3 + 1] - pos[i * 3 + 1] + delta[i * 3 + 1];
    float r2 = pos[j * 3 + 2] - pos[i * 3 + 2] + delta[i * 3 + 2];

    int c = lane * 4;
    float4 yv = *(const float4*)(y + (size_t)j * CC + c);
    float4 w0 = *(const float4*)(f_w + 0 * CC + c);
    float4 w1 = *(const float4*)(f_w + 1 * CC + c);
    float4 w2 = *(const float4*)(f_w + 2 * CC + c);

    float4 z;
    z.x = leaky(yv.x + r0 * w0.x + r1 * w1.x + r2 * w2.x);
    z.y = leaky(yv.y + r0 * w0.y + r1 * w1.y + r2 * w2.y);
    z.z = leaky(yv.z + r0 * w0.z + r1 * w1.z + r2 * w2.z);
    z.w = leaky(yv.w + r0 * w0.w + r1 * w1.w + r2 * w2.w);

    float* dst = aggr + (size_t)i * CC + c;
    asm volatile("red.global.add.v4.f32 [%0], {%1,%2,%3,%4};"
                 :: "l"(dst), "f"(z.x), "f"(z.y), "f"(z.z), "f"(z.w)
                 : "memory");
}

// ---------------------------------------------------------------------------
extern "C" void kernel_launch(void* const* d_in, const int* in_sizes, int n_in,
                              void* d_out, int out_size)
{
    const float* x      = (const float*)d_in[0];
    const float* pos    = (const float*)d_in[1];
    const void*  ei     = d_in[2];
    const float* h_w1   = (const float*)d_in[3];
    const float* h_b1   = (const float*)d_in[4];
    const float* h_w2   = (const float*)d_in[5];
    const float* h_b2   = (const float*)d_in[6];
    const float* f_w    = (const float*)d_in[7];
    const float* f_b    = (const float*)d_in[8];
    const float* g_w1   = (const float*)d_in[9];
    const float* g_b1   = (const float*)d_in[10];
    const float* g_w2   = (const float*)d_in[11];
    const float* g_b2   = (const float*)d_in[12];
    float* out = (float*)d_out;

    const int M = in_sizes[0] / CC;  // 50000
    const int E = in_sizes[2] / 2;   // 800000

    float *y, *t, *aggr, *delta;
    uint4* fragW;
    cudaGetSymbolAddress((void**)&y,     g_y);
    cudaGetSymbolAddress((void**)&t,     g_t);
    cudaGetSymbolAddress((void**)&aggr,  g_aggr);
    cudaGetSymbolAddress((void**)&delta, g_delta);
    cudaGetSymbolAddress((void**)&fragW, g_fragW);

    static int smem_set = 0;
    if (!smem_set) {
        cudaFuncSetAttribute(gemm_mma, cudaFuncAttributeMaxDynamicSharedMemorySize, SM_TOT);
        smem_set = 1;
    }

    const int gcta = (M + 127) / 128;

    // --- prep ---
    detect_dtype_kernel<<<1, 32>>>((const int*)ei, 2048);
    prep_weights_kernel<<<(4 * 4096 + 255) / 256, 256>>>(h_w1, f_w + 3 * CC, g_w1, g_w2);
    zero_kernel<<<(M * CC / 4 + 255) / 256, 256>>>((float4*)aggr, M * CC / 4);

    // --- GEMMs + delta ---
    // delta = tanh(leaky(x @ h_w1 + h_b1) @ h_w2 + h_b2)  (fused, hidden never stored)
    gemm_mma<<<gcta, 512, SM_TOT>>>(x, fragW + 0 * 4096, h_b1, nullptr, nullptr, M, 2,
                                    h_w2, h_b2, delta);
    // y = x @ f_w[3:, :] + f_b
    gemm_mma<<<gcta, 512, SM_TOT>>>(x, fragW + 1 * 4096, f_b, nullptr, y, M, 0,
                                    nullptr, nullptr, nullptr);

    // --- aggregation via atomics ---
    edge_kernel<<<(E + 7) / 8, 256>>>(ei, pos, delta, y, f_w, aggr, E, M);

    // t = leaky(aggr @ g_w1 + g_b1)
    gemm_mma<<<gcta, 512, SM_TOT>>>(aggr, fragW + 2 * 4096, g_b1, nullptr, t, M, 1,
                                    nullptr, nullptr, nullptr);
    // out = t @ g_w2 + g_b2 + x
    gemm_mma<<<gcta, 512, SM_TOT>>>(t, fragW + 3 * 4096, g_b2, x, out, M, 0,
                                    nullptr, nullptr, nullptr);
}